// round 1
// baseline (speedup 1.0000x reference)
#include <cuda_runtime.h>
#include <cstdint>

// TSBRNN: B=8192 rows, T=4096 steps. Two-state swap recurrence per row:
//   A' = (1-beta)*B + beta*nz ; B' = (1-alpha*nz)*A + alpha*X_t*nz ; out = A'*B'
// X_t = x[0,t] (global scalar sequence). DRAM-bound: 256MB total traffic.

namespace {
constexpr int T_LEN    = 4096;
constexpr int ROWS     = 64;          // rows per CTA
constexpr int THREADS  = 64;          // one thread per row
constexpr int TT       = 128;         // timesteps per tile
constexpr int NT       = T_LEN / TT;  // 32 tiles
constexpr int STRIDE   = TT + 4;      // 132 floats per smem row (16B aligned, swizzle-friendly)
constexpr int INSTAGES = 3;
constexpr int INBUF    = ROWS * STRIDE;   // floats
constexpr int OUTBUF   = ROWS * STRIDE;   // floats
constexpr int SMEM_FLOATS = INSTAGES * INBUF + 2 * OUTBUF + T_LEN;
constexpr int SMEM_BYTES  = SMEM_FLOATS * 4;   // 185,344 B
}

__device__ __forceinline__ void cp_async16(uint32_t dst, const void* src) {
    asm volatile("cp.async.cg.shared.global [%0], [%1], 16;\n" :: "r"(dst), "l"(src));
}
__device__ __forceinline__ void cp_commit() {
    asm volatile("cp.async.commit_group;\n" ::: "memory");
}
template <int N>
__device__ __forceinline__ void cp_wait() {
    asm volatile("cp.async.wait_group %0;\n" :: "n"(N) : "memory");
}

// Coalesced tile load: each warp streams full 512B row segments; dst uses a
// per-row rotation of the 16B chunks so compute/store LDS/STS are conflict-free.
__device__ __forceinline__ void load_tile(const float* __restrict__ x, int row_base,
                                          int t0, uint32_t dst_sa, int tid) {
#pragma unroll
    for (int i = 0; i < (ROWS * TT / 4) / THREADS; ++i) {  // 32 float4 per thread
        int idx = tid + THREADS * i;
        int row = idx >> 5;   // 32 float4 per row
        int j4  = idx & 31;
        int js  = (j4 + 2 * ((row >> 3) & 3)) & 31;   // swizzle
        const float* src = x + (size_t)(row_base + row) * T_LEN + t0 + j4 * 4;
        cp_async16(dst_sa + (uint32_t)(row * STRIDE + js * 4) * 4u, src);
    }
}

__global__ void __launch_bounds__(THREADS, 1)
tsb_kernel(const float* __restrict__ x, const float* __restrict__ alpha_p,
           const float* __restrict__ beta_p, float* __restrict__ out) {
    extern __shared__ float smem[];
    float* inb  = smem;
    float* outb = smem + INSTAGES * INBUF;
    float* aX   = outb + 2 * OUTBUF;   // alpha * x[0, t], t in [0,4096)

    const int tid      = threadIdx.x;
    const int row_base = blockIdx.x * ROWS;
    const float alpha  = __ldg(alpha_p);
    const float beta   = __ldg(beta_p);
    const float omb    = 1.0f - beta;
    const float nalpha = -alpha;

    const uint32_t inb_sa = (uint32_t)__cvta_generic_to_shared(inb);

    // Stage the global level-driver sequence: aX[t] = alpha * x[0][t]
#pragma unroll
    for (int i = 0; i < T_LEN / 4 / THREADS; ++i) {   // 16 iterations
        int idx = tid + THREADS * i;
        float4 v = __ldg(reinterpret_cast<const float4*>(x) + idx);
        v.x *= alpha; v.y *= alpha; v.z *= alpha; v.w *= alpha;
        reinterpret_cast<float4*>(aX)[idx] = v;
    }

    // Prologue: fill the 3-deep input pipeline
#pragma unroll
    for (int k = 0; k < INSTAGES; ++k) {
        load_tile(x, row_base, k * TT, inb_sa + (uint32_t)(k * INBUF) * 4u, tid);
        cp_commit();
    }

    float A = 0.0f;   // carry slot 0 (P_next of prev step)
    float Bs = 0.0f;  // carry slot 1 (Z_next of prev step)
    const int swz = 2 * ((tid >> 3) & 3);
    const int w = tid >> 5;
    const int l = tid & 31;

    for (int tile = 0; tile < NT; ++tile) {
        cp_wait<INSTAGES - 1>();
        __syncthreads();   // tile's input visible to all threads (incl. aX on tile 0)

        const float* xrow = inb + (tile % INSTAGES) * INBUF + tid * STRIDE;
        float*       orow = outb + (tile & 1) * OUTBUF + tid * STRIDE;
        const float* aXt  = aX + tile * TT;

#pragma unroll 8
        for (int j4 = 0; j4 < TT / 4; ++j4) {
            int js = (j4 + swz) & 31;
            float4 xv = *reinterpret_cast<const float4*>(xrow + js * 4);
            float4 av = *reinterpret_cast<const float4*>(aXt + j4 * 4);
            float4 o;
            {
                float nz = (xv.x != 0.0f) ? 1.0f : 0.0f;
                float Bn = fmaf(A, fmaf(nalpha, nz, 1.0f), av.x * nz);
                float An = fmaf(Bs, omb, beta * nz);
                o.x = An * Bn; A = An; Bs = Bn;
            }
            {
                float nz = (xv.y != 0.0f) ? 1.0f : 0.0f;
                float Bn = fmaf(A, fmaf(nalpha, nz, 1.0f), av.y * nz);
                float An = fmaf(Bs, omb, beta * nz);
                o.y = An * Bn; A = An; Bs = Bn;
            }
            {
                float nz = (xv.z != 0.0f) ? 1.0f : 0.0f;
                float Bn = fmaf(A, fmaf(nalpha, nz, 1.0f), av.z * nz);
                float An = fmaf(Bs, omb, beta * nz);
                o.z = An * Bn; A = An; Bs = Bn;
            }
            {
                float nz = (xv.w != 0.0f) ? 1.0f : 0.0f;
                float Bn = fmaf(A, fmaf(nalpha, nz, 1.0f), av.w * nz);
                float An = fmaf(Bs, omb, beta * nz);
                o.w = An * Bn; A = An; Bs = Bn;
            }
            *reinterpret_cast<float4*>(orow + js * 4) = o;
        }
        __syncthreads();   // all STS done; input buffer fully consumed

        // Refill the input slot we just consumed (3 tiles ahead)
        int nt = tile + INSTAGES;
        if (nt < NT)
            load_tile(x, row_base, nt * TT,
                      inb_sa + (uint32_t)((nt % INSTAGES) * INBUF) * 4u, tid);
        cp_commit();   // always commit so wait_group accounting stays aligned

        // Coalesced output store: each warp writes full 512B row segments
        const float* ob = outb + (tile & 1) * OUTBUF;
        float* og = out + (size_t)row_base * T_LEN + tile * TT;
#pragma unroll 8
        for (int i = 0; i < 32; ++i) {
            int row = w * 32 + i;
            int js2 = (l + 2 * ((row >> 3) & 3)) & 31;
            float4 v = *reinterpret_cast<const float4*>(ob + row * STRIDE + js2 * 4);
            *reinterpret_cast<float4*>(og + (size_t)row * T_LEN + l * 4) = v;
        }
    }
}

extern "C" void kernel_launch(void* const* d_in, const int* in_sizes, int n_in,
                              void* d_out, int out_size) {
    const float* x       = (const float*)d_in[0];   // (B, T, 1) float32
    const float* alpha_p = (const float*)d_in[1];   // (1, 1)
    const float* beta_p  = (const float*)d_in[2];   // (1, 1)
    float* out = (float*)d_out;

    int batch = in_sizes[0] / T_LEN;                // 8192
    int grid  = batch / ROWS;                       // 128 CTAs

    cudaFuncSetAttribute(tsb_kernel, cudaFuncAttributeMaxDynamicSharedMemorySize,
                         SMEM_BYTES);
    tsb_kernel<<<grid, THREADS, SMEM_BYTES>>>(x, alpha_p, beta_p, out);
}

// round 2
// speedup vs baseline: 1.3670x; 1.3670x over previous
#include <cuda_runtime.h>
#include <cstdint>

// TSBRNN: B=8192 rows, T=4096 steps, per-row 2-state swap recurrence:
//   P' = (1-beta)*carry1 + beta*nz ; Z' = carry0 + nz*(alpha*X_t - alpha*carry0)
//   out = P'*Z' ; carry=(P',Z').  X_t = x[0,t] (row-0 global sequence).
// DRAM-bound: 128MB read + 128MB write. Design: warp-independent execution,
// 8-stage cp.async input pipeline, register-accumulated 32B-sector stores.

namespace {
constexpr int T_LEN   = 4096;
constexpr int TT      = 64;              // timesteps per tile
constexpr int NT      = T_LEN / TT;      // 64 tiles
constexpr int WROWS   = 32;              // rows per warp (1 row/lane)
constexpr int WARPS   = 2;
constexpr int THREADS = 32 * WARPS;      // 64
constexpr int ROWS    = WROWS * WARPS;   // 64 rows per CTA -> grid 128
constexpr int STAGES  = 8;
constexpr int TILE_F  = WROWS * TT;      // 2048 floats = 8KB per stage
constexpr int WBUF_F  = STAGES * TILE_F; // per-warp ring
constexpr int SMEM_FLOATS = WARPS * WBUF_F + T_LEN;
constexpr int SMEM_BYTES  = SMEM_FLOATS * 4;  // 2*64KB + 16KB = 144KB
}

__device__ __forceinline__ void cp_async16(uint32_t dst, const void* src) {
    asm volatile("cp.async.cg.shared.global [%0], [%1], 16;\n" :: "r"(dst), "l"(src));
}
__device__ __forceinline__ void cp_commit() {
    asm volatile("cp.async.commit_group;\n" ::: "memory");
}
template <int N>
__device__ __forceinline__ void cp_wait() {
    asm volatile("cp.async.wait_group %0;\n" :: "n"(N) : "memory");
}

__global__ void __launch_bounds__(THREADS, 1)
tsb_kernel(const float* __restrict__ x, const float* __restrict__ alpha_p,
           const float* __restrict__ beta_p, float* __restrict__ out) {
    extern __shared__ float smem[];
    float* aX = smem + WARPS * WBUF_F;   // alpha * x[0, t]

    const int tid  = threadIdx.x;
    const int wid  = tid >> 5;
    const int lane = tid & 31;
    const float alpha  = __ldg(alpha_p);
    const float beta   = __ldg(beta_p);
    const float omb    = 1.0f - beta;
    const float nalpha = -alpha;

    // One-time staging of the global level-driver sequence (broadcast reads later)
#pragma unroll
    for (int i = 0; i < T_LEN / 4 / THREADS; ++i) {   // 16 float4 per thread
        int idx = tid + THREADS * i;
        float4 v = __ldg(reinterpret_cast<const float4*>(x) + idx);
        v.x *= alpha; v.y *= alpha; v.z *= alpha; v.w *= alpha;
        reinterpret_cast<float4*>(aX)[idx] = v;
    }
    __syncthreads();   // ONLY barrier in the kernel

    const int row_base = blockIdx.x * ROWS + wid * WROWS;
    float* wbuf = smem + wid * WBUF_F;
    const uint32_t wbuf_sa = (uint32_t)__cvta_generic_to_shared(wbuf);
    const float* xbase = x + (size_t)row_base * T_LEN;

    // Per-warp tile load: 16 cp.async per lane, coalesced global, XOR-swizzled smem
    auto load_tile = [&](int tile, int slot) {
        uint32_t sbase = wbuf_sa + (uint32_t)(slot * TILE_F) * 4u;
#pragma unroll
        for (int i = 0; i < 16; ++i) {
            int idx = lane + 32 * i;       // 0..511 (32 rows x 16 float4)
            int row = idx >> 4;
            int j4  = idx & 15;
            int js  = j4 ^ (row & 7);      // conflict-free for compute LDS.128
            const float* src = xbase + (size_t)row * T_LEN + tile * TT + j4 * 4;
            cp_async16(sbase + (uint32_t)(row * TT + js * 4) * 4u, src);
        }
    };

    // Prologue: fill the 8-deep ring
#pragma unroll
    for (int k = 0; k < STAGES; ++k) {
        load_tile(k, k);
        cp_commit();
    }

    float A = 0.0f, Bs = 0.0f;
    const int swz = lane & 7;
    float* og_row = out + (size_t)(row_base + lane) * T_LEN;

#define TSB_STEP(xval, aval, oval)                      \
    {                                                   \
        float nz  = fminf(fabsf(xval), 1.0f);           \
        float bnz = fminf(fabsf(xval), beta);           \
        float t1  = fmaf(nalpha, A, aval);              \
        float Bn  = fmaf(nz, t1, A);                    \
        float An  = fmaf(Bs, omb, bnz);                 \
        oval = An * Bn; A = An; Bs = Bn;                \
    }

    for (int tile = 0; tile < NT; ++tile) {
        cp_wait<STAGES - 1>();   // this warp's oldest group done (per-thread state)

        const float* xr  = wbuf + (tile & (STAGES - 1)) * TILE_F + lane * TT;
        const float* aXt = aX + tile * TT;
        float* og = og_row + tile * TT;

#pragma unroll
        for (int j8 = 0; j8 < TT / 8; ++j8) {
            int j4a = (2 * j8) ^ swz;
            int j4b = j4a ^ 1;            // (2*j8+1) ^ swz
            float4 xv0 = *reinterpret_cast<const float4*>(xr + j4a * 4);
            float4 xv1 = *reinterpret_cast<const float4*>(xr + j4b * 4);
            float4 av0 = *reinterpret_cast<const float4*>(aXt + j8 * 8);
            float4 av1 = *reinterpret_cast<const float4*>(aXt + j8 * 8 + 4);
            float4 o0, o1;
            TSB_STEP(xv0.x, av0.x, o0.x);
            TSB_STEP(xv0.y, av0.y, o0.y);
            TSB_STEP(xv0.z, av0.z, o0.z);
            TSB_STEP(xv0.w, av0.w, o0.w);
            TSB_STEP(xv1.x, av1.x, o1.x);
            TSB_STEP(xv1.y, av1.y, o1.y);
            TSB_STEP(xv1.z, av1.z, o1.z);
            TSB_STEP(xv1.w, av1.w, o1.w);
            // 32B-aligned pair -> one fully-written DRAM sector
            *reinterpret_cast<float4*>(og + j8 * 8)     = o0;
            *reinterpret_cast<float4*>(og + j8 * 8 + 4) = o1;
        }

        // Refill the slot just consumed (all its LDS results already used)
        int nt = tile + STAGES;
        if (nt < NT)
            load_tile(nt, tile & (STAGES - 1));
        cp_commit();   // always commit: keeps wait_group accounting aligned
    }
#undef TSB_STEP
}

extern "C" void kernel_launch(void* const* d_in, const int* in_sizes, int n_in,
                              void* d_out, int out_size) {
    const float* x       = (const float*)d_in[0];   // (B, T, 1) float32
    const float* alpha_p = (const float*)d_in[1];   // (1, 1)
    const float* beta_p  = (const float*)d_in[2];   // (1, 1)
    float* out = (float*)d_out;

    int batch = in_sizes[0] / T_LEN;                // 8192
    int grid  = batch / ROWS;                       // 128 CTAs

    cudaFuncSetAttribute(tsb_kernel, cudaFuncAttributeMaxDynamicSharedMemorySize,
                         SMEM_BYTES);
    tsb_kernel<<<grid, THREADS, SMEM_BYTES>>>(x, alpha_p, beta_p, out);
}